// round 14
// baseline (speedup 1.0000x reference)
#include <cuda_runtime.h>
#include <math.h>

// HybridQuanvolutionClassifier — B=1024, NP=196, KP=4, 10 classes.
// One CTA per batch element, 224 threads (7 warps).
// __launch_bounds__(224, 9) caps regs at 32 -> 9 CTAs/SM -> 148*9 = 1332
// resident CTAs -> the whole 1024-CTA grid runs in ONE wave. (Round 4 showed
// that without the cap, regs grew to 50 and occupancy collapsed to 5 CTAs/SM.)

#define B_    1024
#define NP_   196
#define NC_   10
#define FEAT_ 784
#define THREADS_ 224

__global__ __launch_bounds__(THREADS_, 9)
void hq_kernel(const float* __restrict__ x,      // [1024,1,28,28]
               const float* __restrict__ phi,    // [1024,196,4]
               const float* __restrict__ Wlin,   // [10,784]
               const float* __restrict__ blin,   // [10]
               float* __restrict__ out)          // [1024,10]
{
    const int b = blockIdx.x;
    const int t = threadIdx.x;

    // Interleaved: sNE[2*m] = normalized state, sNE[2*m+1] = expvals.
    // One base address per iteration; +16B folds into the LDS immediate.
    __shared__ float4 sNE[NP_ * 2];
    __shared__ float4 sF4[NP_];   // smoothed feats (patch-major = feat order)
    __shared__ float  sL[NC_];
    __shared__ float  sLse;

    // -------- Phase 1: angles -> expvals (cumprod) + normalized states
    if (t < NP_) {
        const int hp = t / 14;
        const int wp = t - hp * 14;
        const float* xb = x + b * 784;
        const int r0 = (hp * 2) * 28 + wp * 2;
        float th0 = xb[r0];
        float th1 = xb[r0 + 1];
        float th2 = xb[r0 + 28];
        float th3 = xb[r0 + 29];

        float4 ph = ((const float4*)phi)[b * NP_ + t];

        float e0 = cosf(th0) * cosf(ph.x);
        float e1 = e0 * (cosf(th1) * cosf(ph.y));
        float e2 = e1 * (cosf(th2) * cosf(ph.z));
        float e3 = e2 * (cosf(th3) * cosf(ph.w));
        sNE[2 * t + 1] = make_float4(e0, e1, e2, e3);

        float ss  = e0 * e0 + e1 * e1 + e2 * e2 + e3 * e3;
        float inv = 1.0f / (sqrtf(ss) + 1e-12f);
        sNE[2 * t] = make_float4(e0 * inv, e1 * inv, e2 * inv, e3 * inv);
    }
    __syncthreads();

    // -------- Phase 2: graph weights + Laplacian smoothing (row per thread)
    // Self-edge cancels algebraically in (1+deg)*E_t - a, so no m==t branch.
    if (t < NP_) {
        const float4 nt = sNE[2 * t];
        float deg = 0.0f;
        float a0 = 0.0f, a1 = 0.0f, a2 = 0.0f, a3 = 0.0f;

        #pragma unroll 4
        for (int m = 0; m < NP_; m++) {
            float4 nm = sNE[2 * m];
            float4 em = sNE[2 * m + 1];
            float d = nt.x * nm.x;
            d = fmaf(nt.y, nm.y, d);
            d = fmaf(nt.z, nm.z, d);
            d = fmaf(nt.w, nm.w, d);
            float fid = d * d;
            float w = (fid >= 0.8f ? 0.5f : 0.0f) + (fid >= 0.5f ? 0.5f : 0.0f);
            deg += w;
            a0 = fmaf(w, em.x, a0);
            a1 = fmaf(w, em.y, a1);
            a2 = fmaf(w, em.z, a2);
            a3 = fmaf(w, em.w, a3);
        }

        const float4 et = sNE[2 * t + 1];
        const float c = 1.0f + deg;
        sF4[t] = make_float4(fmaf(c, et.x, -a0), fmaf(c, et.y, -a1),
                             fmaf(c, et.z, -a2), fmaf(c, et.w, -a3));
    }
    __syncthreads();

    // -------- Phase 3: logits = feats @ W^T + b (7 warps cover 10 logits)
    const int wi   = t >> 5;
    const int lane = t & 31;
    for (int li = wi; li < NC_; li += 7) {
        const float4* Wr = (const float4*)(Wlin + (size_t)li * FEAT_);
        float acc = 0.0f;
        #pragma unroll
        for (int k = lane; k < NP_; k += 32) {
            float4 wv = Wr[k];
            float4 fv = sF4[k];
            acc = fmaf(wv.x, fv.x, acc);
            acc = fmaf(wv.y, fv.y, acc);
            acc = fmaf(wv.z, fv.z, acc);
            acc = fmaf(wv.w, fv.w, acc);
        }
        #pragma unroll
        for (int o = 16; o > 0; o >>= 1)
            acc += __shfl_down_sync(0xffffffffu, acc, o);
        if (lane == 0) sL[li] = acc + blin[li];
    }
    __syncthreads();

    // -------- log_softmax over 10 classes
    if (t == 0) {
        float mx = sL[0];
        #pragma unroll
        for (int c = 1; c < NC_; c++) mx = fmaxf(mx, sL[c]);
        float s = 0.0f;
        #pragma unroll
        for (int c = 0; c < NC_; c++) s += expf(sL[c] - mx);
        sLse = mx + logf(s);
    }
    __syncthreads();
    if (t < NC_) out[(size_t)b * NC_ + t] = sL[t] - sLse;
}

extern "C" void kernel_launch(void* const* d_in, const int* in_sizes, int n_in,
                              void* d_out, int out_size)
{
    const float* x    = (const float*)d_in[0];
    const float* phi  = (const float*)d_in[1];
    const float* Wlin = (const float*)d_in[2];
    const float* blin = (const float*)d_in[3];
    float* out = (float*)d_out;

    hq_kernel<<<B_, THREADS_>>>(x, phi, Wlin, blin, out);
}